// round 5
// baseline (speedup 1.0000x reference)
#include <cuda_runtime.h>
#include <cstdint>

typedef unsigned long long ull;

// ---------- packed f32x2 helpers (sm_103a) ----------
__device__ __forceinline__ ull pack2(float a, float b) {
    ull r; asm("mov.b64 %0, {%1, %2};" : "=l"(r) : "f"(a), "f"(b)); return r;
}
__device__ __forceinline__ void unpack2(ull v, float& a, float& b) {
    asm("mov.b64 {%0, %1}, %2;" : "=f"(a), "=f"(b) : "l"(v));
}
__device__ __forceinline__ ull ffma2(ull a, ull b, ull c) {
    ull d; asm("fma.rn.f32x2 %0, %1, %2, %3;" : "=l"(d) : "l"(a), "l"(b), "l"(c)); return d;
}
__device__ __forceinline__ ull relu2(ull v) {
    float a, b; unpack2(v, a, b);
    return pack2(fmaxf(a, 0.f), fmaxf(b, 0.f));
}

#define NJ 24
#define JW 104          // ull per joint in full dup image: 13 rows x 8
#define JW2 48          // ull per joint, layer-2-only smem image: 6 rows x 8
#define WPB 8           // warps per block
#define TPAD 74         // tile row stride (EVEN -> aligned STS.64, conflict-free)
#define TILE_FLOATS (64 * TPAD)
#define XS_ULL (24 * 32)                        // packed-x per warp: 6144 B
#define SW2_BYTES (NJ * JW2 * 8)                // 9216
#define SMEM_BYTES (SW2_BYTES + WPB * (XS_ULL * 8 + TILE_FLOATS * 4))  // 209920

// full duplicated weight image (built by prep kernel each launch)
__device__ ull g_dup[NJ * JW];
__constant__ ull c_w[NJ * JW];

// ---- prep: build duplicated-pair weight image ----
__global__ void prep_kernel(const float* __restrict__ W1, const float* __restrict__ b1,
                            const float* __restrict__ W2, const float* __restrict__ b2) {
    int i = blockIdx.x * blockDim.x + threadIdx.x;
    if (i >= NJ * JW) return;
    int j = i / JW, r = i % JW, row = r >> 3, c = r & 7;
    float v;
    if (row < 7) {
        v = (c < 7) ? W1[j * 49 + row * 7 + c] : b1[j * 7 + row];
    } else {
        int rr = row - 7;
        v = (c < 7) ? W2[j * 42 + rr * 7 + c] : b2[j * 6 + rr];
    }
    ull u = (ull)__float_as_uint(v);
    g_dup[i] = u | (u << 32);
}

// ---- layer 2: weights from SMEM (L1 port) ----
__device__ __forceinline__ void layer2(const ull* wp2, const ull* h, ull* fo,
                                       float* fa, float* fb) {
#pragma unroll
    for (int o = 0; o < 6; ++o) {
        const ulonglong2* r = reinterpret_cast<const ulonglong2*>(wp2 + o * 8);
        ulonglong2 q0 = r[0], q1 = r[1], q2 = r[2], q3 = r[3];
        ull acc = ffma2(q0.x, h[0], q3.y);
        acc = ffma2(q0.y, h[1], acc);
        acc = ffma2(q1.x, h[2], acc);
        acc = ffma2(q1.y, h[3], acc);
        acc = ffma2(q2.x, h[4], acc);
        acc = ffma2(q2.y, h[5], acc);
        acc = ffma2(q3.x, h[6], acc);
        float a, b; unpack2(acc, a, b);
        a = fmaxf(a, 0.f); b = fmaxf(b, 0.f);
        fa[o] = a; fb[o] = b;
        fo[o] = pack2(a, b);
    }
}

// ---- layer 1: weights from CONSTANT (const port), J is compile-time ----
template <int J>
__device__ __forceinline__ void joint_fwd(const ull* wp2, ull xp,
                                          const ull* pf, ull* fo,
                                          float* fa, float* fb) {
    ull h[7];
#pragma unroll
    for (int o = 0; o < 7; ++o) {
        const ulonglong2* r = reinterpret_cast<const ulonglong2*>(c_w + J * JW + o * 8);
        ulonglong2 q0 = r[0], q1 = r[1], q2 = r[2], q3 = r[3];
        ull acc = ffma2(q0.x, xp, q3.y);      // w0 * x + bias
        acc = ffma2(q0.y, pf[0], acc);
        acc = ffma2(q1.x, pf[1], acc);
        acc = ffma2(q1.y, pf[2], acc);
        acc = ffma2(q2.x, pf[3], acc);
        acc = ffma2(q2.y, pf[4], acc);
        acc = ffma2(q3.x, pf[5], acc);
        h[o] = relu2(acc);
    }
    layer2(wp2, h, fo, fa, fb);
}

template <int J>
__device__ __forceinline__ void root_fwd(const ull* wp2, ull xp, ull* fo,
                                         float* fa, float* fb) {
    ull h[7];
#pragma unroll
    for (int o = 0; o < 7; ++o) {
        ull w0 = c_w[J * JW + o * 8];
        ull bb = c_w[J * JW + o * 8 + 7];
        h[o] = relu2(ffma2(w0, xp, bb));
    }
    layer2(wp2, h, fo, fa, fb);
}

__global__ void __launch_bounds__(WPB * 32)
StructureEncoder1D_kernel(const float* __restrict__ x,
                          const float* __restrict__ W1,
                          const float* __restrict__ b1,
                          const float* __restrict__ W2,
                          const float* __restrict__ b2,
                          float* __restrict__ out, int B) {
    extern __shared__ __align__(16) char dynsmem[];
    ull*   sw2   = reinterpret_cast<ull*>(dynsmem);                  // layer-2 weights
    ull*   xsall = reinterpret_cast<ull*>(dynsmem + SW2_BYTES);      // packed x
    float* tiles = reinterpret_cast<float*>(dynsmem + SW2_BYTES + WPB * XS_ULL * 8);

    // ---- cooperative fill of layer-2 dup weights (rows 7..12 of dup image) ----
    for (int i = threadIdx.x; i < NJ * JW2; i += blockDim.x) {
        int j = i / JW2, r = i % JW2, row = r >> 3, c = r & 7;
        int rr = row;  // 0..5 -> W2 rows
        float v = (c < 7) ? W2[j * 42 + rr * 7 + c] : b2[j * 6 + rr];
        ull u = (ull)__float_as_uint(v);
        sw2[i] = u | (u << 32);
    }
    __syncthreads();

    const int lane   = threadIdx.x & 31;
    const int warpId = threadIdx.x >> 5;
    const int warpBase = (blockIdx.x * WPB + warpId) * 64;
    if (warpBase >= B) return;

    float* tile = tiles + warpId * TILE_FLOATS;
    ull*   xs   = xsall + warpId * XS_ULL;

    // ---- stage x: coalesced LDG.128 -> padded smem (row stride 25 floats) ----
    {
        const float4* xin = reinterpret_cast<const float4*>(x);
#pragma unroll
        for (int k = 0; k < 12; ++k) {
            int i = k * 32 + lane;               // 64 rows x 6 float4
            int r = i / 6, c = i % 6;
            float4 v = make_float4(0.f, 0.f, 0.f, 0.f);
            if (warpBase + r < B) v = xin[(size_t)(warpBase + r) * 6 + c];
            float* d = tile + r * 25 + c * 4;
            d[0] = v.x; d[1] = v.y; d[2] = v.z; d[3] = v.w;
        }
    }
    __syncwarp();

    // ---- build packed-x region: xs[j*32 + lane] = {x[e0][j], x[e1][j]} ----
#pragma unroll
    for (int j = 0; j < 24; ++j) {
        float a = tile[lane * 25 + j];
        float b = tile[(lane + 32) * 25 + j];
        xs[j * 32 + lane] = pack2(a, b);
    }
    __syncwarp();

    float* ta = tile + lane * TPAD;
    float* tb = tile + (lane + 32) * TPAD;

    ull f0[6], f9[6], cur[6];
    float fa[6], fb[6];

#define XP(J) (xs[(J) * 32 + lane])
#define ST(CB) do {                                                    \
        ((float2*)(ta + (CB)))[0] = make_float2(fa[0], fa[1]);         \
        ((float2*)(ta + (CB)))[1] = make_float2(fa[2], fa[3]);         \
        ((float2*)(ta + (CB)))[2] = make_float2(fa[4], fa[5]);         \
        ((float2*)(tb + (CB)))[0] = make_float2(fb[0], fb[1]);         \
        ((float2*)(tb + (CB)))[1] = make_float2(fb[2], fb[3]);         \
        ((float2*)(tb + (CB)))[2] = make_float2(fb[4], fb[5]);         \
    } while (0)

#define FLUSH(H) do {                                                          \
        __syncwarp();                                                          \
        _Pragma("unroll")                                                      \
        for (int k = 0; k < 36; ++k) {                                         \
            int i = k * 32 + lane;               /* 64 rows x 18 float4 */     \
            int r = i / 18, c = i % 18;                                        \
            if (warpBase + r < B) {                                            \
                const float2* s = reinterpret_cast<const float2*>(             \
                    tile + r * TPAD + c * 4);                                  \
                float2 lo = s[0], hi = s[1];                                   \
                *reinterpret_cast<float4*>(                                    \
                    out + (size_t)(warpBase + r) * 144 + (H) * 72 + c * 4) =   \
                    make_float4(lo.x, lo.y, hi.x, hi.y);                       \
            }                                                                  \
        }                                                                      \
        __syncwarp();                                                          \
    } while (0)

#define W2P(J) (sw2 + (J) * JW2)

    // ---- first half: DFS over joints 0..11 (cols = j*6) ----
    root_fwd <0>(W2P(0),  XP(0),        f0,  fa, fb); ST(0 * 6);
    joint_fwd<1>(W2P(1),  XP(1),  f0,  cur,  fa, fb); ST(1 * 6);
    joint_fwd<4>(W2P(4),  XP(4),  cur, cur,  fa, fb); ST(4 * 6);
    joint_fwd<7>(W2P(7),  XP(7),  cur, cur,  fa, fb); ST(7 * 6);
    joint_fwd<10>(W2P(10), XP(10), cur, cur, fa, fb); ST(10 * 6);
    joint_fwd<2>(W2P(2),  XP(2),  f0,  cur,  fa, fb); ST(2 * 6);
    joint_fwd<5>(W2P(5),  XP(5),  cur, cur,  fa, fb); ST(5 * 6);
    joint_fwd<8>(W2P(8),  XP(8),  cur, cur,  fa, fb); ST(8 * 6);
    joint_fwd<11>(W2P(11), XP(11), cur, cur, fa, fb); ST(11 * 6);
    joint_fwd<3>(W2P(3),  XP(3),  f0,  cur,  fa, fb); ST(3 * 6);
    joint_fwd<6>(W2P(6),  XP(6),  cur, cur,  fa, fb); ST(6 * 6);
    joint_fwd<9>(W2P(9),  XP(9),  cur, f9,   fa, fb); ST(9 * 6);

    FLUSH(0);

    // ---- second half: joints 12..23 (cols = (j-12)*6) ----
    joint_fwd<12>(W2P(12), XP(12), f9,  cur, fa, fb); ST(0 * 6);
    joint_fwd<15>(W2P(15), XP(15), cur, cur, fa, fb); ST(3 * 6);
    joint_fwd<13>(W2P(13), XP(13), f9,  cur, fa, fb); ST(1 * 6);
    joint_fwd<16>(W2P(16), XP(16), cur, cur, fa, fb); ST(4 * 6);
    joint_fwd<18>(W2P(18), XP(18), cur, cur, fa, fb); ST(6 * 6);
    joint_fwd<20>(W2P(20), XP(20), cur, cur, fa, fb); ST(8 * 6);
    joint_fwd<22>(W2P(22), XP(22), cur, cur, fa, fb); ST(10 * 6);
    joint_fwd<14>(W2P(14), XP(14), f9,  cur, fa, fb); ST(2 * 6);
    joint_fwd<17>(W2P(17), XP(17), cur, cur, fa, fb); ST(5 * 6);
    joint_fwd<19>(W2P(19), XP(19), cur, cur, fa, fb); ST(7 * 6);
    joint_fwd<21>(W2P(21), XP(21), cur, cur, fa, fb); ST(9 * 6);
    joint_fwd<23>(W2P(23), XP(23), cur, cur, fa, fb); ST(11 * 6);

    FLUSH(1);

#undef XP
#undef ST
#undef FLUSH
#undef W2P
}

extern "C" void kernel_launch(void* const* d_in, const int* in_sizes, int n_in,
                              void* d_out, int out_size) {
    const float* x  = (const float*)d_in[0];
    const float* W1 = (const float*)d_in[1];
    const float* b1 = (const float*)d_in[2];
    const float* W2 = (const float*)d_in[3];
    const float* b2 = (const float*)d_in[4];
    float* out = (float*)d_out;

    int B = in_sizes[0] / 24;

    // 1) build duplicated weight image on device
    prep_kernel<<<(NJ * JW + 255) / 256, 256>>>(W1, b1, W2, b2);

    // 2) move it into constant memory (D2D async copy — graph-capturable)
    void* src = nullptr;
    cudaGetSymbolAddress(&src, g_dup);
    cudaMemcpyToSymbolAsync(c_w, src, sizeof(ull) * NJ * JW, 0,
                            cudaMemcpyDeviceToDevice, 0);

    // 3) main kernel
    int warps  = (B + 63) / 64;
    int blocks = (warps + WPB - 1) / WPB;
    cudaFuncSetAttribute(StructureEncoder1D_kernel,
                         cudaFuncAttributeMaxDynamicSharedMemorySize, SMEM_BYTES);
    StructureEncoder1D_kernel<<<blocks, WPB * 32, SMEM_BYTES>>>(x, W1, b1, W2, b2, out, B);
}

// round 6
// speedup vs baseline: 1.5064x; 1.5064x over previous
#include <cuda_runtime.h>
#include <cstdint>

typedef unsigned long long ull;

// ---------- packed f32x2 helpers (sm_103a) ----------
__device__ __forceinline__ ull pack2(float a, float b) {
    ull r; asm("mov.b64 %0, {%1, %2};" : "=l"(r) : "f"(a), "f"(b)); return r;
}
__device__ __forceinline__ void unpack2(ull v, float& a, float& b) {
    asm("mov.b64 {%0, %1}, %2;" : "=f"(a), "=f"(b) : "l"(v));
}
__device__ __forceinline__ ull ffma2(ull a, ull b, ull c) {
    ull d; asm("fma.rn.f32x2 %0, %1, %2, %3;" : "=l"(d) : "l"(a), "l"(b), "l"(c)); return d;
}
__device__ __forceinline__ ull relu2(ull v) {
    float a, b; unpack2(v, a, b);
    return pack2(fmaxf(a, 0.f), fmaxf(b, 0.f));
}

#define NJ 24
#define JW 104          // ull per joint: 13 rows x 8 (7 dup weights + dup bias)
#define WPB 12          // warps per block
#define TPAD 38         // quarter-tile row stride in floats (even -> aligned STS.64)
#define TILE_FLOATS (64 * TPAD)                 // 9728 B
#define XS_ULL (24 * 32)                        // packed-x per warp: 6144 B
#define SW_BYTES (NJ * JW * 8)                  // 19968
#define SMEM_BYTES (SW_BYTES + WPB * (XS_ULL * 8 + TILE_FLOATS * 4))  // 210432

// ---- layer 2: 6 outputs from h[7] ----
__device__ __forceinline__ void layer2(const ull* wp, const ull* h, ull* fo,
                                       float* fa, float* fb) {
#pragma unroll
    for (int o = 0; o < 6; ++o) {
        const ulonglong2* r = reinterpret_cast<const ulonglong2*>(wp + 56 + o * 8);
        ulonglong2 q0 = r[0], q1 = r[1], q2 = r[2], q3 = r[3];
        ull acc = ffma2(q0.x, h[0], q3.y);
        acc = ffma2(q0.y, h[1], acc);
        acc = ffma2(q1.x, h[2], acc);
        acc = ffma2(q1.y, h[3], acc);
        acc = ffma2(q2.x, h[4], acc);
        acc = ffma2(q2.y, h[5], acc);
        acc = ffma2(q3.x, h[6], acc);
        float a, b; unpack2(acc, a, b);
        a = fmaxf(a, 0.f); b = fmaxf(b, 0.f);
        fa[o] = a; fb[o] = b;
        fo[o] = pack2(a, b);
    }
}

__device__ __forceinline__ void joint_fwd(const ull* wp, ull xp,
                                          const ull* pf, ull* fo,
                                          float* fa, float* fb) {
    ull h[7];
#pragma unroll
    for (int o = 0; o < 7; ++o) {
        const ulonglong2* r = reinterpret_cast<const ulonglong2*>(wp + o * 8);
        ulonglong2 q0 = r[0], q1 = r[1], q2 = r[2], q3 = r[3];
        ull acc = ffma2(q0.x, xp, q3.y);      // w0 * x + bias
        acc = ffma2(q0.y, pf[0], acc);
        acc = ffma2(q1.x, pf[1], acc);
        acc = ffma2(q1.y, pf[2], acc);
        acc = ffma2(q2.x, pf[3], acc);
        acc = ffma2(q2.y, pf[4], acc);
        acc = ffma2(q3.x, pf[5], acc);
        h[o] = relu2(acc);
    }
    layer2(wp, h, fo, fa, fb);
}

__device__ __forceinline__ void root_fwd(const ull* wp, ull xp, ull* fo,
                                         float* fa, float* fb) {
    ull h[7];
#pragma unroll
    for (int o = 0; o < 7; ++o) {
        ull w0 = wp[o * 8];
        ull bb = wp[o * 8 + 7];
        h[o] = relu2(ffma2(w0, xp, bb));
    }
    layer2(wp, h, fo, fa, fb);
}

__global__ void __launch_bounds__(WPB * 32)
StructureEncoder1D_kernel(const float* __restrict__ x,
                          const float* __restrict__ W1,
                          const float* __restrict__ b1,
                          const float* __restrict__ W2,
                          const float* __restrict__ b2,
                          float* __restrict__ out, int B) {
    extern __shared__ __align__(16) char dynsmem[];
    ull*   sw    = reinterpret_cast<ull*>(dynsmem);                  // dup weights
    ull*   xsall = reinterpret_cast<ull*>(dynsmem + SW_BYTES);       // packed x
    float* tiles = reinterpret_cast<float*>(dynsmem + SW_BYTES + WPB * XS_ULL * 8);

    // ---- cooperative fill: each ull = one weight duplicated into both halves ----
    for (int i = threadIdx.x; i < NJ * JW; i += blockDim.x) {
        int j = i / JW, r = i % JW, row = r >> 3, c = r & 7;
        float v;
        if (row < 7) {
            v = (c < 7) ? W1[j * 49 + row * 7 + c] : b1[j * 7 + row];
        } else {
            int rr = row - 7;
            v = (c < 7) ? W2[j * 42 + rr * 7 + c] : b2[j * 6 + rr];
        }
        ull u = (ull)__float_as_uint(v);
        sw[i] = u | (u << 32);
    }
    __syncthreads();

    const int lane   = threadIdx.x & 31;
    const int warpId = threadIdx.x >> 5;
    const int warpBase = (blockIdx.x * WPB + warpId) * 64;
    if (warpBase >= B) return;

    float* tile = tiles + warpId * (TILE_FLOATS);
    ull*   xs   = xsall + warpId * XS_ULL;

    // ---- stage x: coalesced LDG.128 -> padded smem (row stride 25 floats) ----
    // 64 rows * 25 floats = 1600 floats = 6400 B, fits inside the 9728-B tile
    {
        const float4* xin = reinterpret_cast<const float4*>(x);
#pragma unroll
        for (int k = 0; k < 12; ++k) {
            int i = k * 32 + lane;               // 64 rows x 6 float4
            int r = i / 6, c = i % 6;
            float4 v = make_float4(0.f, 0.f, 0.f, 0.f);
            if (warpBase + r < B) v = xin[(size_t)(warpBase + r) * 6 + c];
            float* d = tile + r * 25 + c * 4;
            d[0] = v.x; d[1] = v.y; d[2] = v.z; d[3] = v.w;
        }
    }
    __syncwarp();

    // ---- build packed-x: xs[j*32 + lane] = {x[e0][j], x[e1][j]} ----
#pragma unroll
    for (int j = 0; j < 24; ++j) {
        float a = tile[lane * 25 + j];
        float b = tile[(lane + 32) * 25 + j];
        xs[j * 32 + lane] = pack2(a, b);
    }
    __syncwarp();

    float* ta = tile + lane * TPAD;
    float* tb = tile + (lane + 32) * TPAD;

    ull fA[6], fB[6], fC[6];
    float fa[6], fb[6];

#define XP(J) (xs[(J) * 32 + lane])
#define WP(J) (sw + (J) * JW)
#define ST(CB) do {                                                    \
        ((float2*)(ta + (CB)))[0] = make_float2(fa[0], fa[1]);         \
        ((float2*)(ta + (CB)))[1] = make_float2(fa[2], fa[3]);         \
        ((float2*)(ta + (CB)))[2] = make_float2(fa[4], fa[5]);         \
        ((float2*)(tb + (CB)))[0] = make_float2(fb[0], fb[1]);         \
        ((float2*)(tb + (CB)))[1] = make_float2(fb[2], fb[3]);         \
        ((float2*)(tb + (CB)))[2] = make_float2(fb[4], fb[5]);         \
    } while (0)

    // flush quarter tile: 64 rows x 36 cols -> out cols [h*36, h*36+36)
#define FLUSH(H) do {                                                          \
        __syncwarp();                                                          \
        _Pragma("unroll")                                                      \
        for (int k = 0; k < 18; ++k) {                                         \
            int i = k * 32 + lane;               /* [0,576): 64 rows x 9 f4 */ \
            int r = i / 9, c = i % 9;                                          \
            if (warpBase + r < B) {                                            \
                const float2* s = reinterpret_cast<const float2*>(             \
                    tile + r * TPAD + c * 4);                                  \
                float2 lo = s[0], hi = s[1];                                   \
                *reinterpret_cast<float4*>(                                    \
                    out + (size_t)(warpBase + r) * 144 + (H) * 36 + c * 4) =   \
                    make_float4(lo.x, lo.y, hi.x, hi.y);                       \
            }                                                                  \
        }                                                                      \
        __syncwarp();                                                          \
    } while (0)

    // ---- phase 0: joints 0..5 (local col = j*6) ----
    root_fwd (WP(0), XP(0),      fA, fa, fb); ST(0 * 6);   // f0 -> fA
    joint_fwd(WP(1), XP(1),  fA, fB, fa, fb); ST(1 * 6);   // f1 -> fB
    joint_fwd(WP(4), XP(4),  fB, fB, fa, fb); ST(4 * 6);   // f4 -> fB
    joint_fwd(WP(2), XP(2),  fA, fC, fa, fb); ST(2 * 6);   // f2 -> fC
    joint_fwd(WP(5), XP(5),  fC, fC, fa, fb); ST(5 * 6);   // f5 -> fC
    joint_fwd(WP(3), XP(3),  fA, fA, fa, fb); ST(3 * 6);   // f3 -> fA
    FLUSH(0);

    // ---- phase 1: joints 6..11 (local col = (j-6)*6) ----
    joint_fwd(WP(6),  XP(6),  fA, fA, fa, fb); ST(0 * 6);  // f6 -> fA
    joint_fwd(WP(9),  XP(9),  fA, fA, fa, fb); ST(3 * 6);  // f9 -> fA
    joint_fwd(WP(7),  XP(7),  fB, fB, fa, fb); ST(1 * 6);  // f7 -> fB
    joint_fwd(WP(10), XP(10), fB, fB, fa, fb); ST(4 * 6);  // f10
    joint_fwd(WP(8),  XP(8),  fC, fC, fa, fb); ST(2 * 6);  // f8 -> fC
    joint_fwd(WP(11), XP(11), fC, fC, fa, fb); ST(5 * 6);  // f11
    FLUSH(1);

    // ---- phase 2: joints 12..17 (local col = (j-12)*6); fA = f9 ----
    joint_fwd(WP(12), XP(12), fA, fB, fa, fb); ST(0 * 6);  // f12 -> fB
    joint_fwd(WP(15), XP(15), fB, fB, fa, fb); ST(3 * 6);  // f15
    joint_fwd(WP(13), XP(13), fA, fB, fa, fb); ST(1 * 6);  // f13 -> fB
    joint_fwd(WP(16), XP(16), fB, fB, fa, fb); ST(4 * 6);  // f16 -> fB (keep)
    joint_fwd(WP(14), XP(14), fA, fC, fa, fb); ST(2 * 6);  // f14 -> fC
    joint_fwd(WP(17), XP(17), fC, fC, fa, fb); ST(5 * 6);  // f17 -> fC (keep)
    FLUSH(2);

    // ---- phase 3: joints 18..23 (local col = (j-18)*6); fB=f16, fC=f17 ----
    joint_fwd(WP(18), XP(18), fB, fB, fa, fb); ST(0 * 6);  // f18 -> fB
    joint_fwd(WP(20), XP(20), fB, fB, fa, fb); ST(2 * 6);  // f20 -> fB
    joint_fwd(WP(22), XP(22), fB, fB, fa, fb); ST(4 * 6);  // f22
    joint_fwd(WP(19), XP(19), fC, fC, fa, fb); ST(1 * 6);  // f19 -> fC
    joint_fwd(WP(21), XP(21), fC, fC, fa, fb); ST(3 * 6);  // f21 -> fC
    joint_fwd(WP(23), XP(23), fC, fC, fa, fb); ST(5 * 6);  // f23
    FLUSH(3);

#undef XP
#undef WP
#undef ST
#undef FLUSH
}

extern "C" void kernel_launch(void* const* d_in, const int* in_sizes, int n_in,
                              void* d_out, int out_size) {
    const float* x  = (const float*)d_in[0];
    const float* W1 = (const float*)d_in[1];
    const float* b1 = (const float*)d_in[2];
    const float* W2 = (const float*)d_in[3];
    const float* b2 = (const float*)d_in[4];
    float* out = (float*)d_out;

    int B = in_sizes[0] / 24;
    int warps  = (B + 63) / 64;
    int blocks = (warps + WPB - 1) / WPB;

    cudaFuncSetAttribute(StructureEncoder1D_kernel,
                         cudaFuncAttributeMaxDynamicSharedMemorySize, SMEM_BYTES);
    StructureEncoder1D_kernel<<<blocks, WPB * 32, SMEM_BYTES>>>(x, W1, b1, W2, b2, out, B);
}